// round 4
// baseline (speedup 1.0000x reference)
#include <cuda_runtime.h>
#include <cstdint>

// QuantumKANRegressor: out[b] = sum_f sum_j kan[f,j] * T_j( tanh( sum_k w[f,k]*T_{k+1}(X[b,f]) / sum_k|w[f,k]| ) )
// B=65536, F=64, DEG=16 (T_1..T_16), KAN_DEG=5 (T_0..T_5)
//
// R4: FEATURE-packed f32x2 (two features of one row per register) -> full
// weight set is 22 packed regs (44 regs), ZERO shared-memory traffic in the
// main loop. 4 rows in flight for ILP, register prefetch, folded reduction.

typedef unsigned long long ull;

__device__ __forceinline__ ull pk2(float lo, float hi) {
    ull d; asm("mov.b64 %0, {%1, %2};" : "=l"(d) : "f"(lo), "f"(hi)); return d;
}
__device__ __forceinline__ void upk2(ull v, float& lo, float& hi) {
    asm("mov.b64 {%0, %1}, %2;" : "=f"(lo), "=f"(hi) : "l"(v));
}
__device__ __forceinline__ ull fma2(ull a, ull b, ull c) {
    ull d; asm("fma.rn.f32x2 %0, %1, %2, %3;" : "=l"(d) : "l"(a), "l"(b), "l"(c)); return d;
}
__device__ __forceinline__ ull add2(ull a, ull b) {
    ull d; asm("add.rn.f32x2 %0, %1, %2;" : "=l"(d) : "l"(a), "l"(b)); return d;
}
__device__ __forceinline__ ull mul2(ull a, ull b) {
    ull d; asm("mul.rn.f32x2 %0, %1, %2;" : "=l"(d) : "l"(a), "l"(b)); return d;
}
__device__ __forceinline__ float ex2f(float x) {
    float y; asm("ex2.approx.f32 %0, %1;" : "=f"(y) : "f"(x)); return y;
}
__device__ __forceinline__ float rcpf(float x) {
    float y; asm("rcp.approx.f32 %0, %1;" : "=f"(y) : "f"(x)); return y;
}
// tanh(f) = 1 - 2/(1 + exp(2f)); exp via ex2 (MUFU). ~1e-6 abs error on |f|<=1.
__device__ __forceinline__ float tanh_fast(float f) {
    float e = ex2f(f * 2.8853900817779268f);   // 2 * log2(e)
    float r = rcpf(e + 1.0f);
    return fmaf(-2.0f, r, 1.0f);
}

static constexpr int F    = 64;
static constexpr int DEG  = 16;
static constexpr int NBLK = 296;   // 2 CTAs/SM * 148 SMs
static constexpr int NTHR = 256;
static constexpr int R    = 4;     // rows in flight per warp-iteration

__global__ void __launch_bounds__(NTHR, 2)
qkan_kernel(const float* __restrict__ X,
            const float* __restrict__ W,    // [F, DEG]
            const float* __restrict__ KC,   // [1, F, 6]
            float* __restrict__ out,        // [B]
            int B)
{
    const int tid  = threadIdx.x;
    const int lane = tid & 31;

    // -------- per-thread weight preprocessing (once) --------
    // Lane owns features f0 = 2*lane, f1 = 2*lane+1, packed as (f0, f1).
    // Sign-folded Chebyshev: X_k = s_k*T_k, s_k = -1 for k mod 4 in {2,3};
    // recurrence X_j = fma( (j odd ? +2x : -2x), X_{j-1}, X_{j-2} ).
    // Folded weight: w'_k = lcu[f][k-1] * s_k / denom[f].
    ull wq[DEG];   // packed (w'_{f0,k}, w'_{f1,k})
    ull pc[6];     // packed KAN monomial (Horner) coefficients per feature
    {
        float wv[2][DEG];
        float rd[2];
        #pragma unroll
        for (int i = 0; i < 2; ++i) {
            const int f = 2 * lane + i;
            float den = 0.0f;
            #pragma unroll
            for (int k = 0; k < DEG; ++k) { wv[i][k] = __ldg(W + f * DEG + k); den += fabsf(wv[i][k]); }
            rd[i] = 1.0f / den;
        }
        #pragma unroll
        for (int k = 0; k < DEG; ++k) {
            const int kk = k + 1;
            float v0 = wv[0][k] * rd[0];
            float v1 = wv[1][k] * rd[1];
            if (kk & 2) { v0 = -v0; v1 = -v1; }
            wq[k] = pk2(v0, v1);
        }
        // KAN Chebyshev (deg 5) -> monomial Horner coefficients, per feature
        float pm[2][6];
        #pragma unroll
        for (int i = 0; i < 2; ++i) {
            const int f = 2 * lane + i;
            const float k0 = __ldg(KC + f*6+0), k1 = __ldg(KC + f*6+1), k2 = __ldg(KC + f*6+2);
            const float k3 = __ldg(KC + f*6+3), k4 = __ldg(KC + f*6+4), k5 = __ldg(KC + f*6+5);
            pm[i][0] = k0 - k2 + k4;
            pm[i][1] = k1 - 3.0f*k3 + 5.0f*k5;
            pm[i][2] = 2.0f*k2 - 8.0f*k4;
            pm[i][3] = 4.0f*k3 - 20.0f*k5;
            pm[i][4] = 8.0f*k4;
            pm[i][5] = 16.0f*k5;
        }
        #pragma unroll
        for (int k = 0; k < 6; ++k) pc[k] = pk2(pm[0][k], pm[1][k]);
    }

    const ull ONE2  = 0x3F8000003F800000ull;   // (1.0f, 1.0f)
    const ull NEG22 = 0xC0000000C0000000ull;   // (-2.0f, -2.0f)

    const int gw = (blockIdx.x * NTHR + tid) >> 5;
    const int nW = (gridDim.x * NTHR) >> 5;
    const int nG = B / R;                      // B divisible by 4

    // ---- prefetch first group (R rows, lane reads its feature pair) ----
    int g = gw;
    float2 cx[R];
    if (g < nG) {
        const float2* base = (const float2*)X + (size_t)(R * g) * 32 + lane;
        #pragma unroll
        for (int r = 0; r < R; ++r) cx[r] = __ldg(base + r * 32);
    }

    while (g < nG) {
        const int gn = g + nW;
        float2 nx[R];
        if (gn < nG) {
            const float2* base = (const float2*)X + (size_t)(R * gn) * 32 + lane;
            #pragma unroll
            for (int r = 0; r < R; ++r) nx[r] = __ldg(base + r * 32);
        }

        // ---- compute R rows with independent chains ----
        float s[R];                            // per-row scalar partial (lane's 2 features)
        {
            ull x[R], p2x[R], m2x[R], Xa[R], Xb[R], feat[R];
            #pragma unroll
            for (int r = 0; r < R; ++r) {
                x[r]   = pk2(cx[r].x, cx[r].y);          // (feat f0, feat f1) of row
                p2x[r] = add2(x[r], x[r]);               // +2x
                m2x[r] = mul2(x[r], NEG22);              // -2x
                Xa[r]  = x[r];                           // X_1
                Xb[r]  = fma2(m2x[r], x[r], ONE2);       // X_2 = 1 - 2x^2
                feat[r] = mul2(wq[0], Xa[r]);
                feat[r] = fma2(wq[1], Xb[r], feat[r]);
            }
            #pragma unroll
            for (int j = 3; j <= DEG; ++j) {
                #pragma unroll
                for (int r = 0; r < R; ++r) {
                    const ull Xc = fma2((j & 1) ? p2x[r] : m2x[r], Xb[r], Xa[r]);
                    feat[r] = fma2(wq[j - 1], Xc, feat[r]);
                    Xa[r] = Xb[r]; Xb[r] = Xc;
                }
            }
            #pragma unroll
            for (int r = 0; r < R; ++r) {
                float lo, hi; upk2(feat[r], lo, hi);
                const ull z = pk2(tanh_fast(lo), tanh_fast(hi));
                ull t = fma2(pc[5], z, pc[4]);
                t = fma2(t, z, pc[3]);
                t = fma2(t, z, pc[2]);
                t = fma2(t, z, pc[1]);
                t = fma2(t, z, pc[0]);
                float tlo, thi; upk2(t, tlo, thi);
                s[r] = tlo + thi;                        // fold lane's two features
            }
        }

        // ---- folded warp reduction over 32 lanes, 4 rows -> 2 packed ----
        {
            const ull A = pk2(s[0], s[1]);               // rows Rg, Rg+1
            const ull Bp = pk2(s[2], s[3]);              // rows Rg+2, Rg+3
            ull m = (lane & 16) ? Bp : A;
            ull o = (lane & 16) ? A  : Bp;
            m = add2(m, __shfl_xor_sync(0xffffffffu, o, 16));
            #pragma unroll
            for (int off = 8; off; off >>= 1)
                m = add2(m, __shfl_xor_sync(0xffffffffu, m, off));
            if ((lane & 15) == 0) {
                float lo, hi; upk2(m, lo, hi);
                // lane 0 -> rows (Rg, Rg+1); lane 16 -> rows (Rg+2, Rg+3)
                ((float2*)out)[2 * g + (lane >> 4)] = make_float2(lo, hi);
            }
        }

        #pragma unroll
        for (int r = 0; r < R; ++r) cx[r] = nx[r];
        g = gn;
    }
}

extern "C" void kernel_launch(void* const* d_in, const int* in_sizes, int n_in,
                              void* d_out, int out_size)
{
    const float* X  = (const float*)d_in[0];   // [B, 64] fp32
    const float* W  = (const float*)d_in[1];   // [64, 16] fp32
    const float* KC = (const float*)d_in[2];   // [1, 64, 6] fp32
    float* out = (float*)d_out;                // [B] fp32

    const int B = in_sizes[0] / F;             // 65536

    qkan_kernel<<<NBLK, NTHR>>>(X, W, KC, out, B);
}